// round 14
// baseline (speedup 1.0000x reference)
#include <cuda_runtime.h>

#define BN    8
#define NPIX  (224*224)   // 50176
#define SS    196
#define EE    768
#define NBLK  49          // blocks per image in k_main
#define TPB   256         // threads per block in k_main
#define PXT   4           // pixels per thread (49*256*4 = 50176 exactly)
#define OROWS 8           // rows per k_out block; 1568/8 = 196 blocks

// Final accumulators. Zero-initialized at load; k_out re-zeroes after use so
// every kernel_launch call (and every graph replay) starts from zeros.
__device__ float g_sum[BN*SS];   // sum (e - 1)   -> D = NPIX + g_sum
__device__ float g_p0 [BN*SS];   // sum e*c0
__device__ float g_p1 [BN*SS];
__device__ float g_p2 [BN*SS];

// Diagnostic no-op: pads the per-call launch count to 5 so ncu's "-s 5 -c 1"
// lands on k_main (launch idx 5 = call 2's k_main) instead of always k_out.
__global__ void k_nop(){}

// Fused pass: per-pixel 196-way argmax + exp(score), warp run-segmented-scan
// aggregation, shared-slot accumulation, per-block flush via global RED.
__global__ __launch_bounds__(TPB) void k_main(
        const float* __restrict__ img,
        const float* __restrict__ Wseg,
        const float* __restrict__ bseg,
        const float* __restrict__ wq){
    __shared__ float4 sW[SS];
    __shared__ float sSum[SS], sP0[SS], sP1[SS], sP2[SS];
    int t = threadIdx.x, lane = t & 31;
    if (t < SS){
        sW[t] = make_float4(Wseg[3*t], Wseg[3*t+1], Wseg[3*t+2], bseg[t]);
        sSum[t]=0.f; sP0[t]=0.f; sP1[t]=0.f; sP2[t]=0.f;
    }
    __syncthreads();

    int b = blockIdx.y;
    const float* im = img + (size_t)b*3*NPIX;
    int n = (blockIdx.x*TPB + t)*PXT;          // 4 consecutive pixels

    float c0[PXT], c1[PXT], c2[PXT];
    {
        float4 u = *(const float4*)(im + n);
        float4 v = *(const float4*)(im + NPIX + n);
        float4 w = *(const float4*)(im + 2*NPIX + n);
        c0[0]=u.x; c0[1]=u.y; c0[2]=u.z; c0[3]=u.w;
        c1[0]=v.x; c1[1]=v.y; c1[2]=v.z; c1[3]=v.w;
        c2[0]=w.x; c2[1]=w.y; c2[2]=w.z; c2[3]=w.w;
    }

    // Argmax: clear low 8 mantissa bits of the logit, embed segment index,
    // carry through a plain fmaxf chain (<=2^-15 rel perturbation; measured
    // 2e-5 end-to-end vs the 1e-3 threshold).
    float best[PXT];
    #pragma unroll
    for (int p = 0; p < PXT; p++) best[p] = -3.4e38f;

    #pragma unroll 4
    for (int s = 0; s < SS; s++){
        float4 w = sW[s];          // one broadcast LDS.128 per 4 pixels
        #pragma unroll
        for (int p = 0; p < PXT; p++){
            float l = fmaf(c0[p], w.x, fmaf(c1[p], w.y, fmaf(c2[p], w.z, w.w)));
            unsigned u = (__float_as_uint(l) & 0xFFFFFF00u) | (unsigned)s;
            best[p] = fmaxf(best[p], __uint_as_float(u));
        }
    }

    float q0 = wq[0], q1 = wq[1], q2 = wq[2];
    #pragma unroll
    for (int p = 0; p < PXT; p++){
        int lbl = __float_as_uint(best[p]) & 0xFFu;
        float e = __expf(fmaf(c0[p], q0, fmaf(c1[p], q1, c2[p]*q2)));
        float v0 = e - 1.0f, v1 = e*c0[p], v2 = e*c1[p], v3 = e*c2[p];

        // run heads: lane 0, or label differs from predecessor
        int prev = __shfl_up_sync(0xffffffffu, lbl, 1);
        bool head = (lane == 0) || (prev != lbl);
        unsigned hm = __ballot_sync(0xffffffffu, head);
        // nearest head at or below this lane (hm bit0 always set)
        int seg_start = 31 - __clz(hm & (0xFFFFFFFFu >> (31 - lane)));

        // inclusive scan, clipped at the run head
        #pragma unroll
        for (int off = 1; off < 32; off <<= 1){
            float a0 = __shfl_up_sync(0xffffffffu, v0, off);
            float a1 = __shfl_up_sync(0xffffffffu, v1, off);
            float a2 = __shfl_up_sync(0xffffffffu, v2, off);
            float a3 = __shfl_up_sync(0xffffffffu, v3, off);
            if (lane - off >= seg_start){
                v0 += a0; v1 += a1; v2 += a2; v3 += a3;
            }
        }
        // tail = last lane of its run (successor is a head, or lane 31)
        bool tail = (lane == 31) || ((hm >> (lane + 1)) & 1u);
        if (tail){
            atomicAdd(&sSum[lbl], v0);
            atomicAdd(&sP0[lbl],  v1);
            atomicAdd(&sP1[lbl],  v2);
            atomicAdd(&sP2[lbl],  v3);
        }
    }
    __syncthreads();

    // flush: no-return global REDs; only 49 ops per address -> low contention
    if (t < SS){
        int bs = b*SS + t;
        atomicAdd(&g_sum[bs], sSum[t]);
        atomicAdd(&g_p0[bs],  sP0[t]);
        atomicAdd(&g_p1[bs],  sP1[t]);
        atomicAdd(&g_p2[bs],  sP2[t]);
    }
}

// Project: 196 blocks x 256 threads, 8 rows each; Wout held in registers
// (3 e-values per thread), stores coalesced. Resets accumulators after use.
__global__ __launch_bounds__(256) void k_out(
        const float* __restrict__ Wout,
        const float* __restrict__ bout,
        float* __restrict__ out){
    __shared__ float4 srow[OROWS];          // (p0,p1,p2,biasScale)
    int t = threadIdx.x;

    float w0[3], w1[3], w2[3], bb[3];
    #pragma unroll
    for (int k = 0; k < 3; k++){
        int e = t + k*256;
        w0[k] = Wout[3*e]; w1[k] = Wout[3*e+1]; w2[k] = Wout[3*e+2];
        bb[k] = bout[e];
    }

    if (t < OROWS){
        int bs = blockIdx.x*OROWS + t;
        float vs = g_sum[bs];
        float v0 = g_p0[bs], v1 = g_p1[bs], v2 = g_p2[bs];
        float4 rv = make_float4(0.f, 0.f, 0.f, 0.f);
        // present <=> any accumulator touched (exact-0 for a present segment
        // is measure-zero: sums of hundreds of random nonzero terms)
        if (vs != 0.f || v0 != 0.f || v1 != 0.f || v2 != 0.f){
            float D   = (float)NPIX + vs;   // = sum(e) over seg + (NPIX-cnt)
            float inv = 1.0f / D;
            rv = make_float4(v0*inv, v1*inv, v2*inv, 1.0f);
        }
        srow[t] = rv;
        g_sum[bs] = 0.f; g_p0[bs] = 0.f; g_p1[bs] = 0.f; g_p2[bs] = 0.f;
    }
    __syncthreads();

    #pragma unroll
    for (int r = 0; r < OROWS; r++){
        float4 p = srow[r];
        float* o = out + (size_t)(blockIdx.x*OROWS + r)*EE;
        #pragma unroll
        for (int k = 0; k < 3; k++){
            // invalid row => p=(0,0,0,0) -> exact 0 (bias suppressed)
            o[t + k*256] = fmaf(p.x, w0[k], fmaf(p.y, w1[k], fmaf(p.z, w2[k], p.w*bb[k])));
        }
    }
}

extern "C" void kernel_launch(void* const* d_in, const int* in_sizes, int n_in,
                              void* d_out, int out_size) {
    const float* img  = (const float*)d_in[0];   // [8,3,224,224]
    const float* Wseg = (const float*)d_in[1];   // [196,3]
    const float* bseg = (const float*)d_in[2];   // [196]
    const float* wq   = (const float*)d_in[3];   // [3]
    const float* Wout = (const float*)d_in[4];   // [768,3]
    const float* bout = (const float*)d_in[5];   // [768]
    float* out = (float*)d_out;                  // [8,196,768]

    dim3 g(NBLK, BN);                            // 392 blocks
    k_main<<<g, TPB>>>(img, Wseg, bseg, wq);
    k_out<<<(BN*SS)/OROWS, 256>>>(Wout, bout, out);   // 196 blocks
    // pad to 5 launches/call so ncu (-s 5 -c 1) profiles k_main next time
    k_nop<<<1, 1>>>();
    k_nop<<<1, 1>>>();
    k_nop<<<1, 1>>>();
}

// round 15
// speedup vs baseline: 1.0815x; 1.0815x over previous
#include <cuda_runtime.h>

#define BN    8
#define NPIX  (224*224)   // 50176
#define SS    196
#define EE    768
#define NBLK  49          // blocks per image
#define TPB   256
#define PXT   4           // pixels per thread (49*256*4 = 50176 exactly)
#define GRID  (BN*NBLK)   // 392 blocks, all resident in wave 1
#define ROWS  4           // rows per block in epilogue; 392*4 = 1568

// Zero-initialized at load; each block re-zeroes the rows it consumes in the
// epilogue, so every kernel_launch call / graph replay starts from zeros.
__device__ float g_sum[BN*SS];   // sum (e - 1)   -> D = NPIX + g_sum
__device__ float g_p0 [BN*SS];   // sum e*c0
__device__ float g_p1 [BN*SS];
__device__ float g_p2 [BN*SS];
// Monotonic arrival counter (never reset -> safe across graph replays;
// target for launch k is (ticket/GRID+1)*GRID).
__device__ unsigned g_arrive;

// Single fused kernel: per-pixel 196-way argmax + exp(score), warp
// run-segmented-scan aggregation, smem accumulation, global RED flush,
// device-wide ticket barrier, then the projection epilogue (4 rows/block).
// One launch per call => ncu's profiled launch is ALWAYS this kernel.
__global__ __launch_bounds__(TPB) void k_fused(
        const float* __restrict__ img,
        const float* __restrict__ Wseg,
        const float* __restrict__ bseg,
        const float* __restrict__ wq,
        const float* __restrict__ Wout,
        const float* __restrict__ bout,
        float* __restrict__ out){
    __shared__ float4 sW[SS];
    __shared__ float sSum[SS], sP0[SS], sP1[SS], sP2[SS];
    int t = threadIdx.x, lane = t & 31;
    int b   = blockIdx.x / NBLK;
    int blk = blockIdx.x - b*NBLK;
    if (t < SS){
        sW[t] = make_float4(Wseg[3*t], Wseg[3*t+1], Wseg[3*t+2], bseg[t]);
        sSum[t]=0.f; sP0[t]=0.f; sP1[t]=0.f; sP2[t]=0.f;
    }
    __syncthreads();

    const float* im = img + (size_t)b*3*NPIX;
    int n = (blk*TPB + t)*PXT;                 // 4 consecutive pixels

    float c0[PXT], c1[PXT], c2[PXT];
    {
        float4 u = *(const float4*)(im + n);
        float4 v = *(const float4*)(im + NPIX + n);
        float4 w = *(const float4*)(im + 2*NPIX + n);
        c0[0]=u.x; c0[1]=u.y; c0[2]=u.z; c0[3]=u.w;
        c1[0]=v.x; c1[1]=v.y; c1[2]=v.z; c1[3]=v.w;
        c2[0]=w.x; c2[1]=w.y; c2[2]=w.z; c2[3]=w.w;
    }

    // Argmax: clear low 8 mantissa bits of the logit, embed segment index,
    // carry through a plain fmaxf chain (<=2^-15 rel perturbation; measured
    // 2e-5 end-to-end vs the 1e-3 threshold).
    float best[PXT];
    #pragma unroll
    for (int p = 0; p < PXT; p++) best[p] = -3.4e38f;

    #pragma unroll 4
    for (int s = 0; s < SS; s++){
        float4 w = sW[s];          // one broadcast LDS.128 per 4 pixels
        #pragma unroll
        for (int p = 0; p < PXT; p++){
            float l = fmaf(c0[p], w.x, fmaf(c1[p], w.y, fmaf(c2[p], w.z, w.w)));
            unsigned u = (__float_as_uint(l) & 0xFFFFFF00u) | (unsigned)s;
            best[p] = fmaxf(best[p], __uint_as_float(u));
        }
    }

    float q0 = wq[0], q1 = wq[1], q2 = wq[2];
    #pragma unroll
    for (int p = 0; p < PXT; p++){
        int lbl = __float_as_uint(best[p]) & 0xFFu;
        float e = __expf(fmaf(c0[p], q0, fmaf(c1[p], q1, c2[p]*q2)));
        float v0 = e - 1.0f, v1 = e*c0[p], v2 = e*c1[p], v3 = e*c2[p];

        // run-segmented scan (heads via ballot; valid for A A B A patterns)
        int prev = __shfl_up_sync(0xffffffffu, lbl, 1);
        bool head = (lane == 0) || (prev != lbl);
        unsigned hm = __ballot_sync(0xffffffffu, head);
        int seg_start = 31 - __clz(hm & (0xFFFFFFFFu >> (31 - lane)));

        #pragma unroll
        for (int off = 1; off < 32; off <<= 1){
            float a0 = __shfl_up_sync(0xffffffffu, v0, off);
            float a1 = __shfl_up_sync(0xffffffffu, v1, off);
            float a2 = __shfl_up_sync(0xffffffffu, v2, off);
            float a3 = __shfl_up_sync(0xffffffffu, v3, off);
            if (lane - off >= seg_start){
                v0 += a0; v1 += a1; v2 += a2; v3 += a3;
            }
        }
        bool tail = (lane == 31) || ((hm >> (lane + 1)) & 1u);
        if (tail){
            atomicAdd(&sSum[lbl], v0);
            atomicAdd(&sP0[lbl],  v1);
            atomicAdd(&sP1[lbl],  v2);
            atomicAdd(&sP2[lbl],  v3);
        }
    }
    __syncthreads();

    // flush: no-return global REDs (49 ops/address)
    if (t < SS){
        int bs = b*SS + t;
        atomicAdd(&g_sum[bs], sSum[t]);
        atomicAdd(&g_p0[bs],  sP0[t]);
        atomicAdd(&g_p1[bs],  sP1[t]);
        atomicAdd(&g_p2[bs],  sP2[t]);
    }

    // ---- device-wide barrier (monotonic ticket; graph-replay safe) ----
    __threadfence();                       // flushes visible before arrival
    __shared__ unsigned s_ticket;
    if (t == 0) s_ticket = atomicAdd(&g_arrive, 1u);
    __syncthreads();
    unsigned target = (s_ticket/GRID + 1u)*GRID;
    if (t == 0){
        while (*(volatile unsigned*)&g_arrive < target) { }
    }
    __syncthreads();
    __threadfence();                       // acquire: see all flushes

    // ---- epilogue: 4 rows per block; reset rows after reading ----
    __shared__ float4 srow[ROWS];          // (p0,p1,p2,biasScale)
    if (t < ROWS){
        int bs = blockIdx.x*ROWS + t;
        float vs = g_sum[bs];
        float v0 = g_p0[bs], v1 = g_p1[bs], v2 = g_p2[bs];
        float4 rv = make_float4(0.f, 0.f, 0.f, 0.f);
        // present <=> any accumulator touched (exact-0 for present segment is
        // measure-zero: sums of hundreds of random nonzero terms)
        if (vs != 0.f || v0 != 0.f || v1 != 0.f || v2 != 0.f){
            float D   = (float)NPIX + vs;  // = sum(e) over seg + (NPIX-cnt)
            float inv = 1.0f / D;
            rv = make_float4(v0*inv, v1*inv, v2*inv, 1.0f);
        }
        srow[t] = rv;
        g_sum[bs] = 0.f; g_p0[bs] = 0.f; g_p1[bs] = 0.f; g_p2[bs] = 0.f;
    }
    __syncthreads();

    #pragma unroll
    for (int r = 0; r < ROWS; r++){
        float4 p = srow[r];
        float* o = out + (size_t)(blockIdx.x*ROWS + r)*EE;
        #pragma unroll
        for (int k = 0; k < 3; k++){
            int e = t + k*256;
            // invalid row => p=(0,0,0,0) -> exact 0 (bias suppressed)
            o[e] = fmaf(p.x, Wout[3*e], fmaf(p.y, Wout[3*e+1],
                       fmaf(p.z, Wout[3*e+2], p.w*bout[e])));
        }
    }
}

extern "C" void kernel_launch(void* const* d_in, const int* in_sizes, int n_in,
                              void* d_out, int out_size) {
    const float* img  = (const float*)d_in[0];   // [8,3,224,224]
    const float* Wseg = (const float*)d_in[1];   // [196,3]
    const float* bseg = (const float*)d_in[2];   // [196]
    const float* wq   = (const float*)d_in[3];   // [3]
    const float* Wout = (const float*)d_in[4];   // [768,3]
    const float* bout = (const float*)d_in[5];   // [768]
    float* out = (float*)d_out;                  // [8,196,768]

    k_fused<<<GRID, TPB>>>(img, Wseg, bseg, wq, Wout, bout, out);
}

// round 16
// speedup vs baseline: 1.1995x; 1.1091x over previous
#include <cuda_runtime.h>

#define BN    8
#define NPIX  (224*224)   // 50176
#define SS    196
#define EE    768
#define NBLK  98          // blocks per image
#define TPB   256
#define PXT   2           // pixels per thread (98*256*2 = 50176 exactly)
#define GRID  (BN*NBLK)   // 784 blocks; launch_bounds(,6) -> all wave-1 resident
#define ROWS  2           // rows per block in epilogue; 784*2 = 1568

// Zero-initialized at load; each block re-zeroes the rows it consumes in the
// epilogue, so every kernel_launch call / graph replay starts from zeros.
__device__ float g_sum[BN*SS];   // sum (e - 1)   -> D = NPIX + g_sum
__device__ float g_p0 [BN*SS];   // sum e*c0
__device__ float g_p1 [BN*SS];
__device__ float g_p2 [BN*SS];
// Monotonic arrival counter (never reset -> safe across graph replays;
// target for launch k is (ticket/GRID+1)*GRID).
__device__ unsigned g_arrive;

// Single fused kernel. R15 profile: issue=45%, occ=33% (grid-limited,
// 2.65 blocks/SM), no pipe saturated => issue-starved. Fix: 784 blocks
// (6 resident/SM guaranteed by __launch_bounds__(256,6)) doubles warps/SMSP.
__global__ __launch_bounds__(TPB, 6) void k_fused(
        const float* __restrict__ img,
        const float* __restrict__ Wseg,
        const float* __restrict__ bseg,
        const float* __restrict__ wq,
        const float* __restrict__ Wout,
        const float* __restrict__ bout,
        float* __restrict__ out){
    __shared__ float4 sW[SS];
    __shared__ float sSum[SS], sP0[SS], sP1[SS], sP2[SS];
    int t = threadIdx.x, lane = t & 31;
    int b   = blockIdx.x / NBLK;
    int blk = blockIdx.x - b*NBLK;
    if (t < SS){
        sW[t] = make_float4(Wseg[3*t], Wseg[3*t+1], Wseg[3*t+2], bseg[t]);
        sSum[t]=0.f; sP0[t]=0.f; sP1[t]=0.f; sP2[t]=0.f;
    }
    __syncthreads();

    const float* im = img + (size_t)b*3*NPIX;
    int n = (blk*TPB + t)*PXT;                 // 2 consecutive pixels

    float c0[PXT], c1[PXT], c2[PXT];
    {
        float2 u = *(const float2*)(im + n);
        float2 v = *(const float2*)(im + NPIX + n);
        float2 w = *(const float2*)(im + 2*NPIX + n);
        c0[0]=u.x; c0[1]=u.y;
        c1[0]=v.x; c1[1]=v.y;
        c2[0]=w.x; c2[1]=w.y;
    }

    // Argmax: clear low 8 mantissa bits of the logit, embed segment index,
    // carry through a plain fmaxf chain (<=2^-15 rel perturbation; measured
    // 2.1e-5 end-to-end vs the 1e-3 threshold).
    float best[PXT];
    #pragma unroll
    for (int p = 0; p < PXT; p++) best[p] = -3.4e38f;

    #pragma unroll 7
    for (int s = 0; s < SS; s++){
        float4 w = sW[s];          // one broadcast LDS.128 per 2 pixels
        #pragma unroll
        for (int p = 0; p < PXT; p++){
            float l = fmaf(c0[p], w.x, fmaf(c1[p], w.y, fmaf(c2[p], w.z, w.w)));
            unsigned u = (__float_as_uint(l) & 0xFFFFFF00u) | (unsigned)s;
            best[p] = fmaxf(best[p], __uint_as_float(u));
        }
    }

    float q0 = wq[0], q1 = wq[1], q2 = wq[2];
    #pragma unroll
    for (int p = 0; p < PXT; p++){
        int lbl = __float_as_uint(best[p]) & 0xFFu;
        float e = __expf(fmaf(c0[p], q0, fmaf(c1[p], q1, c2[p]*q2)));
        float v0 = e - 1.0f, v1 = e*c0[p], v2 = e*c1[p], v3 = e*c2[p];

        // run-segmented scan (heads via ballot; valid for A A B A patterns)
        int prev = __shfl_up_sync(0xffffffffu, lbl, 1);
        bool head = (lane == 0) || (prev != lbl);
        unsigned hm = __ballot_sync(0xffffffffu, head);
        int seg_start = 31 - __clz(hm & (0xFFFFFFFFu >> (31 - lane)));

        #pragma unroll
        for (int off = 1; off < 32; off <<= 1){
            float a0 = __shfl_up_sync(0xffffffffu, v0, off);
            float a1 = __shfl_up_sync(0xffffffffu, v1, off);
            float a2 = __shfl_up_sync(0xffffffffu, v2, off);
            float a3 = __shfl_up_sync(0xffffffffu, v3, off);
            if (lane - off >= seg_start){
                v0 += a0; v1 += a1; v2 += a2; v3 += a3;
            }
        }
        bool tail = (lane == 31) || ((hm >> (lane + 1)) & 1u);
        if (tail){
            atomicAdd(&sSum[lbl], v0);
            atomicAdd(&sP0[lbl],  v1);
            atomicAdd(&sP1[lbl],  v2);
            atomicAdd(&sP2[lbl],  v3);
        }
    }
    __syncthreads();

    // flush: no-return global REDs (98 ops/address)
    if (t < SS){
        int bs = b*SS + t;
        atomicAdd(&g_sum[bs], sSum[t]);
        atomicAdd(&g_p0[bs],  sP0[t]);
        atomicAdd(&g_p1[bs],  sP1[t]);
        atomicAdd(&g_p2[bs],  sP2[t]);
    }

    // ---- device-wide barrier (monotonic ticket; graph-replay safe) ----
    __threadfence();                       // flushes visible before arrival
    __shared__ unsigned s_ticket;
    if (t == 0) s_ticket = atomicAdd(&g_arrive, 1u);
    __syncthreads();
    unsigned target = (s_ticket/GRID + 1u)*GRID;
    if (t == 0){
        while (*(volatile unsigned*)&g_arrive < target) { }
    }
    __syncthreads();
    __threadfence();                       // acquire: see all flushes

    // ---- epilogue: 2 rows per block; reset rows after reading ----
    __shared__ float4 srow[ROWS];          // (p0,p1,p2,biasScale)
    if (t < ROWS){
        int bs = blockIdx.x*ROWS + t;
        float vs = g_sum[bs];
        float v0 = g_p0[bs], v1 = g_p1[bs], v2 = g_p2[bs];
        float4 rv = make_float4(0.f, 0.f, 0.f, 0.f);
        // present <=> any accumulator touched (exact-0 for present segment is
        // measure-zero: sums of hundreds of random nonzero terms)
        if (vs != 0.f || v0 != 0.f || v1 != 0.f || v2 != 0.f){
            float D   = (float)NPIX + vs;  // = sum(e) over seg + (NPIX-cnt)
            float inv = 1.0f / D;
            rv = make_float4(v0*inv, v1*inv, v2*inv, 1.0f);
        }
        srow[t] = rv;
        g_sum[bs] = 0.f; g_p0[bs] = 0.f; g_p1[bs] = 0.f; g_p2[bs] = 0.f;
    }
    __syncthreads();

    #pragma unroll
    for (int r = 0; r < ROWS; r++){
        float4 p = srow[r];
        float* o = out + (size_t)(blockIdx.x*ROWS + r)*EE;
        #pragma unroll
        for (int k = 0; k < 3; k++){
            int e = t + k*256;
            // invalid row => p=(0,0,0,0) -> exact 0 (bias suppressed)
            o[e] = fmaf(p.x, Wout[3*e], fmaf(p.y, Wout[3*e+1],
                       fmaf(p.z, Wout[3*e+2], p.w*bout[e])));
        }
    }
}

extern "C" void kernel_launch(void* const* d_in, const int* in_sizes, int n_in,
                              void* d_out, int out_size) {
    const float* img  = (const float*)d_in[0];   // [8,3,224,224]
    const float* Wseg = (const float*)d_in[1];   // [196,3]
    const float* bseg = (const float*)d_in[2];   // [196]
    const float* wq   = (const float*)d_in[3];   // [3]
    const float* Wout = (const float*)d_in[4];   // [768,3]
    const float* bout = (const float*)d_in[5];   // [768]
    float* out = (float*)d_out;                  // [8,196,768]

    k_fused<<<GRID, TPB>>>(img, Wseg, bseg, wq, Wout, bout, out);
}